// round 12
// baseline (speedup 1.0000x reference)
#include <cuda_runtime.h>
#include <math.h>

#define B_  64
#define T_  1024
#define I_  256
#define H_  512
#define G_  2048          // 4*H
#define BH_ (B_*H_)       // 32768
#define BG_ (B_*G_)       // 131072

// ---------------- scratch (device globals; no allocation allowed) ----------------
__device__ float g_Wih[G_*H_];              // permuted input weights (gate-interleaved rows), max K=512
__device__ float g_Whh[G_*H_];              // permuted recurrent weights
__device__ float g_bias[G_];                // b_ih + b_hh, permuted
__device__ float g_xp[(size_t)T_*B_*G_];    // precomputed x@W_ih + bias, layout [t][b][g']
__device__ float g_y0[(size_t)T_*B_*H_];    // layer-0 outputs, layout [t][b][h]
__device__ float g_h[2][BH_];               // h ping-pong
__device__ unsigned g_arrive;               // grid-barrier cumulative arrivals
__device__ unsigned g_release;              // grid-barrier release step

// ---------------- weight permutation: g' = 4*j + gate  <-  g = gate*H + j ----------------
__global__ void permute_kernel(const float* __restrict__ Wih,
                               const float* __restrict__ Whh,
                               const float* __restrict__ bih,
                               const float* __restrict__ bhh,
                               int Kin) {
    int total = G_*Kin + G_*H_ + G_;
    for (int e = blockIdx.x*blockDim.x + threadIdx.x; e < total; e += gridDim.x*blockDim.x) {
        if (e < G_*Kin) {
            int gp = e / Kin, col = e - gp*Kin;
            int j = gp >> 2, q = gp & 3;
            g_Wih[gp*Kin + col] = Wih[(q*H_ + j)*Kin + col];
        } else if (e < G_*Kin + G_*H_) {
            int e2 = e - G_*Kin;
            int gp = e2 / H_, col = e2 - gp*H_;
            int j = gp >> 2, q = gp & 3;
            g_Whh[gp*H_ + col] = Whh[(q*H_ + j)*H_ + col];
        } else {
            int gp = e - G_*Kin - G_*H_;
            int j = gp >> 2, q = gp & 3;
            g_bias[gp] = bih[q*H_ + j] + bhh[q*H_ + j];
        }
    }
}

__global__ void zero_hc_kernel() {
    int i = blockIdx.x*blockDim.x + threadIdx.x;
    if (i == 0) { g_arrive = 0u; g_release = 0u; }
    if (i < BH_) { g_h[0][i] = 0.f; }
}

// ---------------- precompute GEMM: xp[t,b,g'] = sum_i A[(b,t),i]*Wp[g',i] + bias[g'] ----------------
// mode 0: A = x, element (r=b*T+t, i) at x[b*I*T + i*T + t]   (layer 0, K=I)
// mode 1: A = g_y0, element at g_y0[t*B*H + b*H + i]          (layer 1, K=H)
// tile 128x128x16, 256 threads, 8x8 register tile computed as 8x4 f32x2 pairs
__global__ __launch_bounds__(256, 2)
void gemm_xp_kernel(const float* __restrict__ X, int K, int mode) {
    __shared__ float As[16][132];
    __shared__ float Bs[16][132];
    const int n0 = blockIdx.x * 128;
    const int m0 = blockIdx.y * 128;
    const int b  = m0 >> 10;          // tiles never cross a batch boundary (128 | 1024)
    const int t0 = m0 & 1023;
    const int tid = threadIdx.x;
    const int ty = tid >> 4, tx = tid & 15;
    const int row0 = ty * 8, col0 = tx * 8;

    unsigned long long accp[8][4];
#pragma unroll
    for (int i = 0; i < 8; i++)
#pragma unroll
        for (int j = 0; j < 4; j++) accp[i][j] = 0ull;

    for (int k0 = 0; k0 < K; k0 += 16) {
        if (mode == 0) {
            const int m4 = (tid & 31) * 4;
            const int kk = tid >> 5;
#pragma unroll
            for (int it = 0; it < 2; it++) {
                int k = kk + it * 8;
                float4 v = *(const float4*)(X + (size_t)b*(I_*T_) + (size_t)(k0+k)*T_ + t0 + m4);
                *(float4*)&As[k][m4] = v;
            }
        } else {
            const int kq = tid & 3;
            const int mm = tid >> 2;
#pragma unroll
            for (int it = 0; it < 2; it++) {
                int m = mm + it * 64;
                float4 v = *(const float4*)(g_y0 + (size_t)(t0+m)*BH_ + (size_t)b*H_ + k0 + kq*4);
                As[kq*4+0][m] = v.x; As[kq*4+1][m] = v.y;
                As[kq*4+2][m] = v.z; As[kq*4+3][m] = v.w;
            }
        }
        {
            const int kq = tid & 3;
            const int nn = tid >> 2;
#pragma unroll
            for (int it = 0; it < 2; it++) {
                int n = nn + it * 64;
                float4 v = *(const float4*)(g_Wih + (size_t)(n0+n)*K + k0 + kq*4);
                Bs[kq*4+0][n] = v.x; Bs[kq*4+1][n] = v.y;
                Bs[kq*4+2][n] = v.z; Bs[kq*4+3][n] = v.w;
            }
        }
        __syncthreads();
#pragma unroll
        for (int k = 0; k < 16; k++) {
            float a[8];
            *(float4*)&a[0] = *(const float4*)&As[k][row0];
            *(float4*)&a[4] = *(const float4*)&As[k][row0+4];
            const ulonglong2 w01 = *(const ulonglong2*)&Bs[k][col0];     // (w0,w1),(w2,w3)
            const ulonglong2 w23 = *(const ulonglong2*)&Bs[k][col0+4];   // (w4,w5),(w6,w7)
#pragma unroll
            for (int i = 0; i < 8; i++) {
                unsigned long long ad;
                asm("mov.b64 %0, {%1,%1};" : "=l"(ad) : "f"(a[i]));
                asm("fma.rn.f32x2 %0, %1, %2, %0;" : "+l"(accp[i][0]) : "l"(ad), "l"(w01.x));
                asm("fma.rn.f32x2 %0, %1, %2, %0;" : "+l"(accp[i][1]) : "l"(ad), "l"(w01.y));
                asm("fma.rn.f32x2 %0, %1, %2, %0;" : "+l"(accp[i][2]) : "l"(ad), "l"(w23.x));
                asm("fma.rn.f32x2 %0, %1, %2, %0;" : "+l"(accp[i][3]) : "l"(ad), "l"(w23.y));
            }
        }
        __syncthreads();
    }
    // epilogue: unpack, add bias, write xp[t][b][g'] vectorized
    float bw[8];
#pragma unroll
    for (int j = 0; j < 8; j++) bw[j] = g_bias[n0 + col0 + j];
#pragma unroll
    for (int i = 0; i < 8; i++) {
        float o[8];
#pragma unroll
        for (int j = 0; j < 4; j++)
            asm("mov.b64 {%0,%1}, %2;" : "=f"(o[2*j]), "=f"(o[2*j+1]) : "l"(accp[i][j]));
        int t = t0 + row0 + i;
        size_t base = (size_t)t*BG_ + (size_t)b*G_ + n0 + col0;
        float4 v0 = make_float4(o[0]+bw[0], o[1]+bw[1], o[2]+bw[2], o[3]+bw[3]);
        float4 v1 = make_float4(o[4]+bw[4], o[5]+bw[5], o[6]+bw[6], o[7]+bw[7]);
        *(float4*)&g_xp[base]     = v0;
        *(float4*)&g_xp[base + 4] = v1;
    }
}

// ---------------- persistent recurrence: all 1024 steps in ONE kernel ----------------
// grid = 128 blocks (one wave, <=148 SMs -> spin grid-barrier is safe).
// Block bx owns hidden units [4*bx, 4*bx+4) = 16 gate-interleaved columns.
// Whh slice lives in smem (duplicated f32x2 pairs) for the whole sequence.
// Cell state c lives in registers for the whole sequence.
// Per-step GEMM 64x16x512 with packed fma.rn.f32x2 (2 batch rows per op).
#define HS_STRIDE 76   // floats; 304B rows: 16B-aligned, 2-way-max STS conflict
__global__ __launch_bounds__(256)
void lstm_seq_kernel(int layer, float* __restrict__ dout) {
    extern __shared__ unsigned char sm[];
    unsigned long long* Wp = (unsigned long long*)sm;               // [512][16] dup pairs, 64 KB
    float* Hs = (float*)(sm + 65536);                                // [64][HS_STRIDE], 19456 B
    float* Gs = (float*)(sm + 65536 + 64*HS_STRIDE*4);               // [64][17], 4352 B
    const int tid = threadIdx.x;
    const int bx  = blockIdx.x;
    const int n0  = bx * 16;
    const int col  = tid & 15;
    const int row0 = (tid >> 4) << 2;       // 4 batch rows per thread
    const int kq  = tid & 15;               // staging k-quad
    const int bb0 = tid >> 4;               // staging batch base
    const int pb = tid >> 2;                // pointwise batch
    const int pu = tid & 3;                 // pointwise unit-in-block
    const int pj = bx*4 + pu;               // pointwise hidden index

    // Load this block's Whh slice once, duplicated into f32x2 pairs.
    for (int idx = tid; idx < 512*16; idx += 256) {
        int cc = idx & 15, kk = idx >> 4;
        float w = g_Whh[(size_t)(n0 + cc)*H_ + kk];
        ((float2*)Wp)[idx] = make_float2(w, w);
    }

    float c_reg = 0.f;

    for (int t = 0; t < T_; t++) {
        const float* __restrict__ h_in  = g_h[t & 1];
        float*       __restrict__ h_out = g_h[(t & 1) ^ 1];

        // prefetch this thread's xp values (HBM, latency hidden under GEMM)
        const float* xpp = g_xp + (size_t)t*BG_ + n0 + col;
        float x0 = __ldcg(xpp + (size_t)(row0+0)*G_);
        float x1 = __ldcg(xpp + (size_t)(row0+1)*G_);
        float x2 = __ldcg(xpp + (size_t)(row0+2)*G_);
        float x3 = __ldcg(xpp + (size_t)(row0+3)*G_);

        unsigned long long acc01 = 0ull, acc23 = 0ull;
        float4 pf[4];
#pragma unroll
        for (int it = 0; it < 4; it++)
            pf[it] = __ldcg((const float4*)(h_in + (size_t)(bb0 + it*16)*H_ + kq*4));

        for (int c = 0; c < 8; c++) {            // 8 chunks of 64 k
            __syncthreads();                      // previous chunk compute done
#pragma unroll
            for (int it = 0; it < 4; it++) {
                int bb = bb0 + it*16;
                Hs[(kq*4+0)*HS_STRIDE + bb] = pf[it].x;
                Hs[(kq*4+1)*HS_STRIDE + bb] = pf[it].y;
                Hs[(kq*4+2)*HS_STRIDE + bb] = pf[it].z;
                Hs[(kq*4+3)*HS_STRIDE + bb] = pf[it].w;
            }
            if (c < 7) {                          // prefetch next chunk (L2, latency hidden)
#pragma unroll
                for (int it = 0; it < 4; it++)
                    pf[it] = __ldcg((const float4*)(h_in + (size_t)(bb0 + it*16)*H_ + (c+1)*64 + kq*4));
            }
            __syncthreads();
            const unsigned long long* wrow = Wp + ((c << 6) * 16) + col;
#pragma unroll
            for (int k = 0; k < 64; k++) {
                unsigned long long w = wrow[k*16];
                ulonglong2 h2 = *(const ulonglong2*)(Hs + k*HS_STRIDE + row0);
                asm("fma.rn.f32x2 %0, %1, %2, %0;" : "+l"(acc01) : "l"(h2.x), "l"(w));
                asm("fma.rn.f32x2 %0, %1, %2, %0;" : "+l"(acc23) : "l"(h2.y), "l"(w));
            }
        }
        float a0, a1, a2, a3;
        asm("mov.b64 {%0,%1}, %2;" : "=f"(a0), "=f"(a1) : "l"(acc01));
        asm("mov.b64 {%0,%1}, %2;" : "=f"(a2), "=f"(a3) : "l"(acc23));
        Gs[(row0+0)*17 + col] = a0 + x0;
        Gs[(row0+1)*17 + col] = a1 + x1;
        Gs[(row0+2)*17 + col] = a2 + x2;
        Gs[(row0+3)*17 + col] = a3 + x3;
        __syncthreads();
        {   // pointwise LSTM cell update: one (batch, unit) per thread; c in register
            float gi = Gs[pb*17 + pu*4+0];
            float gf = Gs[pb*17 + pu*4+1];
            float gg = Gs[pb*17 + pu*4+2];
            float go = Gs[pb*17 + pu*4+3];
            float iv = 1.f / (1.f + expf(-gi));
            float fv = 1.f / (1.f + expf(-gf));
            float gv = tanhf(gg);
            float ov = 1.f / (1.f + expf(-go));
            c_reg = fv * c_reg + iv * gv;
            float hv = ov * tanhf(c_reg);
            __stcg(h_out + pb*H_ + pj, hv);
            if (layer == 0) g_y0[(size_t)t*BH_ + pb*H_ + pj] = hv;
            else            dout[(size_t)pb*(T_*H_) + (size_t)t*H_ + pj] = hv;
            if (t == T_-1) {
                size_t base = (size_t)B_ * T_ * H_;
                dout[base + (size_t)layer*BH_     + pb*H_ + pj] = hv;     // hT
                dout[base + (size_t)(2+layer)*BH_ + pb*H_ + pj] = c_reg;  // cT
            }
        }
        // grid barrier: all h_out writes visible before any block starts step t+1
        if (t < T_-1) {
            __threadfence();
            __syncthreads();
            if (tid == 0) {
                unsigned target = (unsigned)(t + 1);
                unsigned prev = atomicAdd(&g_arrive, 1u);
                if (prev == target*128u - 1u) {
                    atomicExch(&g_release, target);
                } else {
                    while (*((volatile unsigned*)&g_release) < target) { }
                }
            }
            __syncthreads();
        }
    }
}

#define DYN_SMEM (65536 + 64*HS_STRIDE*4 + 64*17*4)

extern "C" void kernel_launch(void* const* d_in, const int* in_sizes, int n_in,
                              void* d_out, int out_size) {
    const float* x    = (const float*)d_in[0];
    const float* Wih0 = (const float*)d_in[1];
    const float* Whh0 = (const float*)d_in[2];
    const float* bih0 = (const float*)d_in[3];
    const float* bhh0 = (const float*)d_in[4];
    const float* Wih1 = (const float*)d_in[5];
    const float* Whh1 = (const float*)d_in[6];
    const float* bih1 = (const float*)d_in[7];
    const float* bhh1 = (const float*)d_in[8];
    float* out = (float*)d_out;

    cudaFuncSetAttribute(lstm_seq_kernel,
                         cudaFuncAttributeMaxDynamicSharedMemorySize, DYN_SMEM);

    // ---- layer 0 ----
    permute_kernel<<<2048, 256>>>(Wih0, Whh0, bih0, bhh0, I_);
    gemm_xp_kernel<<<dim3(16, 512), 256>>>(x, I_, 0);
    zero_hc_kernel<<<(BH_ + 255) / 256, 256>>>();
    lstm_seq_kernel<<<128, 256, DYN_SMEM>>>(0, out);

    // ---- layer 1 ----
    permute_kernel<<<2048, 256>>>(Wih1, Whh1, bih1, bhh1, H_);
    gemm_xp_kernel<<<dim3(16, 512), 256>>>(nullptr, H_, 1);
    zero_hc_kernel<<<(BH_ + 255) / 256, 256>>>();
    lstm_seq_kernel<<<128, 256, DYN_SMEM>>>(1, out);
}

// round 14
// speedup vs baseline: 1.0004x; 1.0004x over previous
#include <cuda_runtime.h>
#include <math.h>

#define B_  64
#define T_  1024
#define I_  256
#define H_  512
#define G_  2048          // 4*H
#define BH_ (B_*H_)       // 32768
#define BG_ (B_*G_)       // 131072

// ---------------- scratch (device globals; no allocation allowed) ----------------
__device__ float g_Wih[G_*H_];              // permuted input weights (gate-interleaved rows), max K=512
__device__ float g_Whh[G_*H_];              // permuted recurrent weights
__device__ float g_bias[G_];                // b_ih + b_hh, permuted
__device__ float g_xp[(size_t)T_*B_*G_];    // precomputed x@W_ih + bias, layout [t][b][g']
__device__ float g_y0[(size_t)T_*B_*H_];    // layer-0 outputs, layout [t][b][h]
__device__ float g_h[2][BH_];               // h ping-pong
__device__ unsigned g_arrive;               // grid-barrier cumulative arrivals
__device__ unsigned g_release;              // grid-barrier release step

// ---------------- weight permutation: g' = 4*j + gate  <-  g = gate*H + j ----------------
__global__ void permute_kernel(const float* __restrict__ Wih,
                               const float* __restrict__ Whh,
                               const float* __restrict__ bih,
                               const float* __restrict__ bhh,
                               int Kin) {
    int total = G_*Kin + G_*H_ + G_;
    for (int e = blockIdx.x*blockDim.x + threadIdx.x; e < total; e += gridDim.x*blockDim.x) {
        if (e < G_*Kin) {
            int gp = e / Kin, col = e - gp*Kin;
            int j = gp >> 2, q = gp & 3;
            g_Wih[gp*Kin + col] = Wih[(q*H_ + j)*Kin + col];
        } else if (e < G_*Kin + G_*H_) {
            int e2 = e - G_*Kin;
            int gp = e2 / H_, col = e2 - gp*H_;
            int j = gp >> 2, q = gp & 3;
            g_Whh[gp*H_ + col] = Whh[(q*H_ + j)*H_ + col];
        } else {
            int gp = e - G_*Kin - G_*H_;
            int j = gp >> 2, q = gp & 3;
            g_bias[gp] = bih[q*H_ + j] + bhh[q*H_ + j];
        }
    }
}

__global__ void zero_hc_kernel() {
    int i = blockIdx.x*blockDim.x + threadIdx.x;
    if (i == 0) { g_arrive = 0u; g_release = 0u; }
    if (i < BH_) { g_h[0][i] = 0.f; }
}

// ---------------- precompute GEMM: xp[t,b,g'] = sum_i A[(b,t),i]*Wp[g',i] + bias[g'] ----------------
// mode 0: A = x, element (r=b*T+t, i) at x[b*I*T + i*T + t]   (layer 0, K=I)
// mode 1: A = g_y0, element at g_y0[t*B*H + b*H + i]          (layer 1, K=H)
// tile 128x128x16, 256 threads, 8x8 register tile computed as 8x4 f32x2 pairs
__global__ __launch_bounds__(256, 2)
void gemm_xp_kernel(const float* __restrict__ X, int K, int mode) {
    __shared__ float As[16][132];
    __shared__ float Bs[16][132];
    const int n0 = blockIdx.x * 128;
    const int m0 = blockIdx.y * 128;
    const int b  = m0 >> 10;          // tiles never cross a batch boundary (128 | 1024)
    const int t0 = m0 & 1023;
    const int tid = threadIdx.x;
    const int ty = tid >> 4, tx = tid & 15;
    const int row0 = ty * 8, col0 = tx * 8;

    unsigned long long accp[8][4];
#pragma unroll
    for (int i = 0; i < 8; i++)
#pragma unroll
        for (int j = 0; j < 4; j++) accp[i][j] = 0ull;

    for (int k0 = 0; k0 < K; k0 += 16) {
        if (mode == 0) {
            const int m4 = (tid & 31) * 4;
            const int kk = tid >> 5;
#pragma unroll
            for (int it = 0; it < 2; it++) {
                int k = kk + it * 8;
                float4 v = *(const float4*)(X + (size_t)b*(I_*T_) + (size_t)(k0+k)*T_ + t0 + m4);
                *(float4*)&As[k][m4] = v;
            }
        } else {
            const int kq = tid & 3;
            const int mm = tid >> 2;
#pragma unroll
            for (int it = 0; it < 2; it++) {
                int m = mm + it * 64;
                float4 v = *(const float4*)(g_y0 + (size_t)(t0+m)*BH_ + (size_t)b*H_ + k0 + kq*4);
                As[kq*4+0][m] = v.x; As[kq*4+1][m] = v.y;
                As[kq*4+2][m] = v.z; As[kq*4+3][m] = v.w;
            }
        }
        {
            const int kq = tid & 3;
            const int nn = tid >> 2;
#pragma unroll
            for (int it = 0; it < 2; it++) {
                int n = nn + it * 64;
                float4 v = *(const float4*)(g_Wih + (size_t)(n0+n)*K + k0 + kq*4);
                Bs[kq*4+0][n] = v.x; Bs[kq*4+1][n] = v.y;
                Bs[kq*4+2][n] = v.z; Bs[kq*4+3][n] = v.w;
            }
        }
        __syncthreads();
#pragma unroll
        for (int k = 0; k < 16; k++) {
            float a[8];
            *(float4*)&a[0] = *(const float4*)&As[k][row0];
            *(float4*)&a[4] = *(const float4*)&As[k][row0+4];
            const ulonglong2 w01 = *(const ulonglong2*)&Bs[k][col0];     // (w0,w1),(w2,w3)
            const ulonglong2 w23 = *(const ulonglong2*)&Bs[k][col0+4];   // (w4,w5),(w6,w7)
#pragma unroll
            for (int i = 0; i < 8; i++) {
                unsigned long long ad;
                asm("mov.b64 %0, {%1,%1};" : "=l"(ad) : "f"(a[i]));
                asm("fma.rn.f32x2 %0, %1, %2, %0;" : "+l"(accp[i][0]) : "l"(ad), "l"(w01.x));
                asm("fma.rn.f32x2 %0, %1, %2, %0;" : "+l"(accp[i][1]) : "l"(ad), "l"(w01.y));
                asm("fma.rn.f32x2 %0, %1, %2, %0;" : "+l"(accp[i][2]) : "l"(ad), "l"(w23.x));
                asm("fma.rn.f32x2 %0, %1, %2, %0;" : "+l"(accp[i][3]) : "l"(ad), "l"(w23.y));
            }
        }
        __syncthreads();
    }
    // epilogue: unpack, add bias, write xp[t][b][g'] vectorized
    float bw[8];
#pragma unroll
    for (int j = 0; j < 8; j++) bw[j] = g_bias[n0 + col0 + j];
#pragma unroll
    for (int i = 0; i < 8; i++) {
        float o[8];
#pragma unroll
        for (int j = 0; j < 4; j++)
            asm("mov.b64 {%0,%1}, %2;" : "=f"(o[2*j]), "=f"(o[2*j+1]) : "l"(accp[i][j]));
        int t = t0 + row0 + i;
        size_t base = (size_t)t*BG_ + (size_t)b*G_ + n0 + col0;
        float4 v0 = make_float4(o[0]+bw[0], o[1]+bw[1], o[2]+bw[2], o[3]+bw[3]);
        float4 v1 = make_float4(o[4]+bw[4], o[5]+bw[5], o[6]+bw[6], o[7]+bw[7]);
        *(float4*)&g_xp[base]     = v0;
        *(float4*)&g_xp[base + 4] = v1;
    }
}

// ---------------- persistent recurrence: all 1024 steps in ONE kernel ----------------
// grid = 128 blocks (one wave, <=148 SMs -> spin grid-barrier is safe).
// Block bx owns hidden units [4*bx, 4*bx+4) = 16 gate-interleaved columns.
// Whh slice lives in smem (duplicated f32x2 pairs) for the whole sequence.
// Cell state c lives in registers for the whole sequence.
// Per-step GEMM 64x16x512 with packed fma.rn.f32x2 (2 batch rows per op).
#define HS_STRIDE 76   // floats; 304B rows: 16B-aligned, 2-way-max STS conflict
__global__ __launch_bounds__(256)
void lstm_seq_kernel(int layer, float* __restrict__ dout) {
    extern __shared__ unsigned char sm[];
    unsigned long long* Wp = (unsigned long long*)sm;               // [512][16] dup pairs, 64 KB
    float* Hs = (float*)(sm + 65536);                                // [64][HS_STRIDE], 19456 B
    float* Gs = (float*)(sm + 65536 + 64*HS_STRIDE*4);               // [64][17], 4352 B
    const int tid = threadIdx.x;
    const int bx  = blockIdx.x;
    const int n0  = bx * 16;
    const int col  = tid & 15;
    const int row0 = (tid >> 4) << 2;       // 4 batch rows per thread
    const int kq  = tid & 15;               // staging k-quad
    const int bb0 = tid >> 4;               // staging batch base
    const int pb = tid >> 2;                // pointwise batch
    const int pu = tid & 3;                 // pointwise unit-in-block
    const int pj = bx*4 + pu;               // pointwise hidden index

    // Load this block's Whh slice once, duplicated into f32x2 pairs.
    for (int idx = tid; idx < 512*16; idx += 256) {
        int cc = idx & 15, kk = idx >> 4;
        float w = g_Whh[(size_t)(n0 + cc)*H_ + kk];
        ((float2*)Wp)[idx] = make_float2(w, w);
    }

    float c_reg = 0.f;

    for (int t = 0; t < T_; t++) {
        const float* __restrict__ h_in  = g_h[t & 1];
        float*       __restrict__ h_out = g_h[(t & 1) ^ 1];

        // prefetch this thread's xp values (HBM, latency hidden under GEMM)
        const float* xpp = g_xp + (size_t)t*BG_ + n0 + col;
        float x0 = __ldcg(xpp + (size_t)(row0+0)*G_);
        float x1 = __ldcg(xpp + (size_t)(row0+1)*G_);
        float x2 = __ldcg(xpp + (size_t)(row0+2)*G_);
        float x3 = __ldcg(xpp + (size_t)(row0+3)*G_);

        unsigned long long acc01 = 0ull, acc23 = 0ull;
        float4 pf[4];
#pragma unroll
        for (int it = 0; it < 4; it++)
            pf[it] = __ldcg((const float4*)(h_in + (size_t)(bb0 + it*16)*H_ + kq*4));

        for (int c = 0; c < 8; c++) {            // 8 chunks of 64 k
            __syncthreads();                      // previous chunk compute done
#pragma unroll
            for (int it = 0; it < 4; it++) {
                int bb = bb0 + it*16;
                Hs[(kq*4+0)*HS_STRIDE + bb] = pf[it].x;
                Hs[(kq*4+1)*HS_STRIDE + bb] = pf[it].y;
                Hs[(kq*4+2)*HS_STRIDE + bb] = pf[it].z;
                Hs[(kq*4+3)*HS_STRIDE + bb] = pf[it].w;
            }
            if (c < 7) {                          // prefetch next chunk (L2, latency hidden)
#pragma unroll
                for (int it = 0; it < 4; it++)
                    pf[it] = __ldcg((const float4*)(h_in + (size_t)(bb0 + it*16)*H_ + (c+1)*64 + kq*4));
            }
            __syncthreads();
            const unsigned long long* wrow = Wp + ((c << 6) * 16) + col;
#pragma unroll
            for (int k = 0; k < 64; k++) {
                unsigned long long w = wrow[k*16];
                ulonglong2 h2 = *(const ulonglong2*)(Hs + k*HS_STRIDE + row0);
                asm("fma.rn.f32x2 %0, %1, %2, %0;" : "+l"(acc01) : "l"(h2.x), "l"(w));
                asm("fma.rn.f32x2 %0, %1, %2, %0;" : "+l"(acc23) : "l"(h2.y), "l"(w));
            }
        }
        float a0, a1, a2, a3;
        asm("mov.b64 {%0,%1}, %2;" : "=f"(a0), "=f"(a1) : "l"(acc01));
        asm("mov.b64 {%0,%1}, %2;" : "=f"(a2), "=f"(a3) : "l"(acc23));
        Gs[(row0+0)*17 + col] = a0 + x0;
        Gs[(row0+1)*17 + col] = a1 + x1;
        Gs[(row0+2)*17 + col] = a2 + x2;
        Gs[(row0+3)*17 + col] = a3 + x3;
        __syncthreads();
        {   // pointwise LSTM cell update: one (batch, unit) per thread; c in register
            float gi = Gs[pb*17 + pu*4+0];
            float gf = Gs[pb*17 + pu*4+1];
            float gg = Gs[pb*17 + pu*4+2];
            float go = Gs[pb*17 + pu*4+3];
            float iv = 1.f / (1.f + expf(-gi));
            float fv = 1.f / (1.f + expf(-gf));
            float gv = tanhf(gg);
            float ov = 1.f / (1.f + expf(-go));
            c_reg = fv * c_reg + iv * gv;
            float hv = ov * tanhf(c_reg);
            __stcg(h_out + pb*H_ + pj, hv);
            if (layer == 0) g_y0[(size_t)t*BH_ + pb*H_ + pj] = hv;
            else            dout[(size_t)pb*(T_*H_) + (size_t)t*H_ + pj] = hv;
            if (t == T_-1) {
                size_t base = (size_t)B_ * T_ * H_;
                dout[base + (size_t)layer*BH_     + pb*H_ + pj] = hv;     // hT
                dout[base + (size_t)(2+layer)*BH_ + pb*H_ + pj] = c_reg;  // cT
            }
        }
        // grid barrier: all h_out writes visible before any block starts step t+1
        if (t < T_-1) {
            __threadfence();
            __syncthreads();
            if (tid == 0) {
                unsigned target = (unsigned)(t + 1);
                unsigned prev = atomicAdd(&g_arrive, 1u);
                if (prev == target*128u - 1u) {
                    atomicExch(&g_release, target);
                } else {
                    while (*((volatile unsigned*)&g_release) < target) { }
                }
            }
            __syncthreads();
        }
    }
}

#define DYN_SMEM (65536 + 64*HS_STRIDE*4 + 64*17*4)

extern "C" void kernel_launch(void* const* d_in, const int* in_sizes, int n_in,
                              void* d_out, int out_size) {
    const float* x    = (const float*)d_in[0];
    const float* Wih0 = (const float*)d_in[1];
    const float* Whh0 = (const float*)d_in[2];
    const float* bih0 = (const float*)d_in[3];
    const float* bhh0 = (const float*)d_in[4];
    const float* Wih1 = (const float*)d_in[5];
    const float* Whh1 = (const float*)d_in[6];
    const float* bih1 = (const float*)d_in[7];
    const float* bhh1 = (const float*)d_in[8];
    float* out = (float*)d_out;

    cudaFuncSetAttribute(lstm_seq_kernel,
                         cudaFuncAttributeMaxDynamicSharedMemorySize, DYN_SMEM);

    // ---- layer 0 ----
    permute_kernel<<<2048, 256>>>(Wih0, Whh0, bih0, bhh0, I_);
    gemm_xp_kernel<<<dim3(16, 512), 256>>>(x, I_, 0);
    zero_hc_kernel<<<(BH_ + 255) / 256, 256>>>();
    lstm_seq_kernel<<<128, 256, DYN_SMEM>>>(0, out);

    // ---- layer 1 ----
    permute_kernel<<<2048, 256>>>(Wih1, Whh1, bih1, bhh1, H_);
    gemm_xp_kernel<<<dim3(16, 512), 256>>>(nullptr, H_, 1);
    zero_hc_kernel<<<(BH_ + 255) / 256, 256>>>();
    lstm_seq_kernel<<<128, 256, DYN_SMEM>>>(1, out);
}

// round 15
// speedup vs baseline: 1.6030x; 1.6023x over previous
#include <cuda_runtime.h>
#include <math.h>

#define B_  64
#define T_  1024
#define I_  256
#define H_  512
#define G_  2048          // 4*H
#define BH_ (B_*H_)       // 32768
#define BG_ (B_*G_)       // 131072

// ---------------- scratch (device globals; no allocation allowed) ----------------
__device__ float g_Wih[G_*H_];              // permuted input weights (gate-interleaved rows), max K=512
__device__ float g_Whh[G_*H_];              // permuted recurrent weights
__device__ float g_bias[G_];                // b_ih + b_hh, permuted
__device__ float g_xp[(size_t)T_*B_*G_];    // precomputed x@W_ih + bias, layout [t][b][g']
__device__ float g_y0[(size_t)T_*B_*H_];    // layer-0 outputs, layout [t][b][h]
__device__ float g_h[2][BH_];               // h ping-pong
__device__ unsigned g_arrive;               // grid-barrier cumulative arrivals
__device__ unsigned g_release;              // grid-barrier release step

__device__ __forceinline__ float tanh_ap(float x) {
    float y; asm("tanh.approx.f32 %0, %1;" : "=f"(y) : "f"(x)); return y;
}
__device__ __forceinline__ float sig_ap(float x) {
    return 0.5f * tanh_ap(0.5f * x) + 0.5f;
}

// ---------------- weight permutation: g' = 4*j + gate  <-  g = gate*H + j ----------------
__global__ void permute_kernel(const float* __restrict__ Wih,
                               const float* __restrict__ Whh,
                               const float* __restrict__ bih,
                               const float* __restrict__ bhh,
                               int Kin) {
    int total = G_*Kin + G_*H_ + G_;
    for (int e = blockIdx.x*blockDim.x + threadIdx.x; e < total; e += gridDim.x*blockDim.x) {
        if (e < G_*Kin) {
            int gp = e / Kin, col = e - gp*Kin;
            int j = gp >> 2, q = gp & 3;
            g_Wih[gp*Kin + col] = Wih[(q*H_ + j)*Kin + col];
        } else if (e < G_*Kin + G_*H_) {
            int e2 = e - G_*Kin;
            int gp = e2 / H_, col = e2 - gp*H_;
            int j = gp >> 2, q = gp & 3;
            g_Whh[gp*H_ + col] = Whh[(q*H_ + j)*H_ + col];
        } else {
            int gp = e - G_*Kin - G_*H_;
            int j = gp >> 2, q = gp & 3;
            g_bias[gp] = bih[q*H_ + j] + bhh[q*H_ + j];
        }
    }
}

__global__ void zero_hc_kernel() {
    int i = blockIdx.x*blockDim.x + threadIdx.x;
    if (i == 0) { g_arrive = 0u; g_release = 0u; }
    if (i < BH_) { g_h[0][i] = 0.f; }
}

// ---------------- precompute GEMM: xp[t,b,g'] = sum_i A[(b,t),i]*Wp[g',i] + bias[g'] ----------------
__global__ __launch_bounds__(256, 2)
void gemm_xp_kernel(const float* __restrict__ X, int K, int mode) {
    __shared__ float As[16][132];
    __shared__ float Bs[16][132];
    const int n0 = blockIdx.x * 128;
    const int m0 = blockIdx.y * 128;
    const int b  = m0 >> 10;          // tiles never cross a batch boundary (128 | 1024)
    const int t0 = m0 & 1023;
    const int tid = threadIdx.x;
    const int ty = tid >> 4, tx = tid & 15;
    const int row0 = ty * 8, col0 = tx * 8;

    unsigned long long accp[8][4];
#pragma unroll
    for (int i = 0; i < 8; i++)
#pragma unroll
        for (int j = 0; j < 4; j++) accp[i][j] = 0ull;

    for (int k0 = 0; k0 < K; k0 += 16) {
        if (mode == 0) {
            const int m4 = (tid & 31) * 4;
            const int kk = tid >> 5;
#pragma unroll
            for (int it = 0; it < 2; it++) {
                int k = kk + it * 8;
                float4 v = *(const float4*)(X + (size_t)b*(I_*T_) + (size_t)(k0+k)*T_ + t0 + m4);
                *(float4*)&As[k][m4] = v;
            }
        } else {
            const int kq = tid & 3;
            const int mm = tid >> 2;
#pragma unroll
            for (int it = 0; it < 2; it++) {
                int m = mm + it * 64;
                float4 v = *(const float4*)(g_y0 + (size_t)(t0+m)*BH_ + (size_t)b*H_ + k0 + kq*4);
                As[kq*4+0][m] = v.x; As[kq*4+1][m] = v.y;
                As[kq*4+2][m] = v.z; As[kq*4+3][m] = v.w;
            }
        }
        {
            const int kq = tid & 3;
            const int nn = tid >> 2;
#pragma unroll
            for (int it = 0; it < 2; it++) {
                int n = nn + it * 64;
                float4 v = *(const float4*)(g_Wih + (size_t)(n0+n)*K + k0 + kq*4);
                Bs[kq*4+0][n] = v.x; Bs[kq*4+1][n] = v.y;
                Bs[kq*4+2][n] = v.z; Bs[kq*4+3][n] = v.w;
            }
        }
        __syncthreads();
#pragma unroll
        for (int k = 0; k < 16; k++) {
            float a[8];
            *(float4*)&a[0] = *(const float4*)&As[k][row0];
            *(float4*)&a[4] = *(const float4*)&As[k][row0+4];
            const ulonglong2 w01 = *(const ulonglong2*)&Bs[k][col0];
            const ulonglong2 w23 = *(const ulonglong2*)&Bs[k][col0+4];
#pragma unroll
            for (int i = 0; i < 8; i++) {
                unsigned long long ad;
                asm("mov.b64 %0, {%1,%1};" : "=l"(ad) : "f"(a[i]));
                asm("fma.rn.f32x2 %0, %1, %2, %0;" : "+l"(accp[i][0]) : "l"(ad), "l"(w01.x));
                asm("fma.rn.f32x2 %0, %1, %2, %0;" : "+l"(accp[i][1]) : "l"(ad), "l"(w01.y));
                asm("fma.rn.f32x2 %0, %1, %2, %0;" : "+l"(accp[i][2]) : "l"(ad), "l"(w23.x));
                asm("fma.rn.f32x2 %0, %1, %2, %0;" : "+l"(accp[i][3]) : "l"(ad), "l"(w23.y));
            }
        }
        __syncthreads();
    }
    float bw[8];
#pragma unroll
    for (int j = 0; j < 8; j++) bw[j] = g_bias[n0 + col0 + j];
#pragma unroll
    for (int i = 0; i < 8; i++) {
        float o[8];
#pragma unroll
        for (int j = 0; j < 4; j++)
            asm("mov.b64 {%0,%1}, %2;" : "=f"(o[2*j]), "=f"(o[2*j+1]) : "l"(accp[i][j]));
        int t = t0 + row0 + i;
        size_t base = (size_t)t*BG_ + (size_t)b*G_ + n0 + col0;
        float4 v0 = make_float4(o[0]+bw[0], o[1]+bw[1], o[2]+bw[2], o[3]+bw[3]);
        float4 v1 = make_float4(o[4]+bw[4], o[5]+bw[5], o[6]+bw[6], o[7]+bw[7]);
        *(float4*)&g_xp[base]     = v0;
        *(float4*)&g_xp[base + 4] = v1;
    }
}

// ---------------- persistent recurrence: all 1024 steps in ONE kernel ----------------
// grid = 128 blocks (one wave). Block bx owns hidden units [4*bx,4*bx+4) = 16 gate cols.
// Whh slice resident in smem as duplicated f32x2 pairs (64 KB).
// Thread tile: 4 rows x 4 cols x K-split-4 -> 8 independent FFMA2 chains,
// 3 LDS.128 per 32 MACs. Hs chunk uses XOR swizzle (bb4 ^ k4), no padding:
// staging STS is 2-way max, GEMM row reads conflict-free.
// Cell state c lives in a register for the whole sequence.
#define GS_STRIDE 20
__global__ __launch_bounds__(256)
void lstm_seq_kernel(int layer, float* __restrict__ dout) {
    extern __shared__ unsigned char sm[];
    unsigned long long* Wp = (unsigned long long*)sm;   // [512][16] dup pairs, 64 KB
    float* Hsf = (float*)(sm + 65536);                  // [64 k][64 bb] swizzled, 16 KB
    float* Gs  = (float*)(sm + 65536 + 16384);          // [4 ks][64 b][GS_STRIDE], 20.5 KB
    const int tid = threadIdx.x;
    const int bx  = blockIdx.x;
    const int n0  = bx * 16;
    // GEMM tiling
    const int rg = tid & 15;            // row group: rows r0..r0+3
    const int cg = (tid >> 4) & 3;      // col group: cols c0..c0+3
    const int ks = tid >> 6;            // k slice within each 64-k chunk: [ks*16, ks*16+16)
    const int r0 = rg * 4;
    const int c0 = cg * 4;
    const int x0s = rg ^ (ks << 2);     // swizzle seed
    // staging
    const int kq  = tid & 15;
    const int bb0 = tid >> 4;
    // pointwise
    const int pb = tid >> 2;
    const int pu = tid & 3;
    const int pj = bx*4 + pu;

    // Load this block's Whh slice once, duplicated into f32x2 pairs: Wp[k*16 + col]
    for (int idx = tid; idx < 512*16; idx += 256) {
        int cc = idx & 15, kk = idx >> 4;
        float w = g_Whh[(size_t)(n0 + cc)*H_ + kk];
        ((float2*)Wp)[idx] = make_float2(w, w);
    }

    float c_reg = 0.f;

    for (int t = 0; t < T_; t++) {
        const float* __restrict__ h_in  = g_h[t & 1];
        float*       __restrict__ h_out = g_h[(t & 1) ^ 1];

        // prefetch xp (i,f,g,o for this thread's (batch, unit)) — latency hidden under GEMM
        float4 xpv = __ldcg((const float4*)(g_xp + (size_t)t*BG_ + (size_t)pb*G_ + n0 + pu*4));

        unsigned long long acc[2][4];
#pragma unroll
        for (int rp = 0; rp < 2; rp++)
#pragma unroll
            for (int cc = 0; cc < 4; cc++) acc[rp][cc] = 0ull;

        float4 pf[4];
#pragma unroll
        for (int it = 0; it < 4; it++)
            pf[it] = __ldcg((const float4*)(h_in + (size_t)(bb0 + it*16)*H_ + kq*4));

        for (int c = 0; c < 8; c++) {            // 8 chunks of 64 k
            __syncthreads();                      // previous chunk compute done
#pragma unroll
            for (int it = 0; it < 4; it++) {
                int bb = bb0 + it*16;
                int sw = ((((bb >> 2) ^ kq) & 15) << 2) | (bb & 3);
                Hsf[(kq*4+0)*64 + sw] = pf[it].x;
                Hsf[(kq*4+1)*64 + sw] = pf[it].y;
                Hsf[(kq*4+2)*64 + sw] = pf[it].z;
                Hsf[(kq*4+3)*64 + sw] = pf[it].w;
            }
            if (c < 7) {                          // prefetch next chunk
#pragma unroll
                for (int it = 0; it < 4; it++)
                    pf[it] = __ldcg((const float4*)(h_in + (size_t)(bb0 + it*16)*H_ + (c+1)*64 + kq*4));
            }
            __syncthreads();
            const unsigned long long* wb = Wp + (size_t)(c*64 + ks*16)*16 + c0;
#pragma unroll
            for (int kk = 0; kk < 16; kk++) {
                int kl = ks*16 + kk;
                ulonglong2 w01 = *(const ulonglong2*)(wb + kk*16);
                ulonglong2 w23 = *(const ulonglong2*)(wb + kk*16 + 2);
                int hoff = kl*64 + (((x0s ^ (kk >> 2)) & 15) << 2);
                ulonglong2 h2 = *(const ulonglong2*)(Hsf + hoff);
                asm("fma.rn.f32x2 %0, %1, %2, %0;" : "+l"(acc[0][0]) : "l"(h2.x), "l"(w01.x));
                asm("fma.rn.f32x2 %0, %1, %2, %0;" : "+l"(acc[0][1]) : "l"(h2.x), "l"(w01.y));
                asm("fma.rn.f32x2 %0, %1, %2, %0;" : "+l"(acc[0][2]) : "l"(h2.x), "l"(w23.x));
                asm("fma.rn.f32x2 %0, %1, %2, %0;" : "+l"(acc[0][3]) : "l"(h2.x), "l"(w23.y));
                asm("fma.rn.f32x2 %0, %1, %2, %0;" : "+l"(acc[1][0]) : "l"(h2.y), "l"(w01.x));
                asm("fma.rn.f32x2 %0, %1, %2, %0;" : "+l"(acc[1][1]) : "l"(h2.y), "l"(w01.y));
                asm("fma.rn.f32x2 %0, %1, %2, %0;" : "+l"(acc[1][2]) : "l"(h2.y), "l"(w23.x));
                asm("fma.rn.f32x2 %0, %1, %2, %0;" : "+l"(acc[1][3]) : "l"(h2.y), "l"(w23.y));
            }
        }
        // unpack partials and park in Gs[ks]
        {
            float v[4][4];
#pragma unroll
            for (int rp = 0; rp < 2; rp++)
#pragma unroll
                for (int cc = 0; cc < 4; cc++)
                    asm("mov.b64 {%0,%1}, %2;" : "=f"(v[2*rp][cc]), "=f"(v[2*rp+1][cc]) : "l"(acc[rp][cc]));
#pragma unroll
            for (int i = 0; i < 4; i++)
                *(float4*)&Gs[ks*(64*GS_STRIDE) + (r0+i)*GS_STRIDE + c0] =
                    make_float4(v[i][0], v[i][1], v[i][2], v[i][3]);
        }
        __syncthreads();
        {   // pointwise: reduce over 4 k-slices, apply LSTM cell; c in register
            float4 s = xpv;
#pragma unroll
            for (int q = 0; q < 4; q++) {
                float4 g = *(const float4*)&Gs[q*(64*GS_STRIDE) + pb*GS_STRIDE + pu*4];
                s.x += g.x; s.y += g.y; s.z += g.z; s.w += g.w;
            }
            float iv = sig_ap(s.x);
            float fv = sig_ap(s.y);
            float gv = tanh_ap(s.z);
            float ov = sig_ap(s.w);
            c_reg = fv * c_reg + iv * gv;
            float hv = ov * tanh_ap(c_reg);
            __stcg(h_out + pb*H_ + pj, hv);
            if (layer == 0) g_y0[(size_t)t*BH_ + pb*H_ + pj] = hv;
            else            dout[(size_t)pb*(T_*H_) + (size_t)t*H_ + pj] = hv;
            if (t == T_-1) {
                size_t base = (size_t)B_ * T_ * H_;
                dout[base + (size_t)layer*BH_     + pb*H_ + pj] = hv;     // hT
                dout[base + (size_t)(2+layer)*BH_ + pb*H_ + pj] = c_reg;  // cT
            }
        }
        // grid barrier: all h_out writes visible before any block starts step t+1
        if (t < T_-1) {
            __threadfence();
            __syncthreads();
            if (tid == 0) {
                unsigned target = (unsigned)(t + 1);
                unsigned prev = atomicAdd(&g_arrive, 1u);
                if (prev == target*128u - 1u) {
                    atomicExch(&g_release, target);
                } else {
                    while (*((volatile unsigned*)&g_release) < target) { }
                }
            }
            __syncthreads();
        }
    }
}

#define DYN_SMEM (65536 + 16384 + 4*64*GS_STRIDE*4)

extern "C" void kernel_launch(void* const* d_in, const int* in_sizes, int n_in,
                              void* d_out, int out_size) {
    const float* x    = (const float*)d_in[0];
    const float* Wih0 = (const float*)d_in[1];
    const float* Whh0 = (const float*)d_in[2];
    const float* bih0 = (const float*)d_in[3];
    const float* bhh0 = (const float*)d_in[4];
    const float* Wih1 = (const float*)d_in[5];
    const float* Whh1 = (const float*)d_in[6];
    const float* bih1 = (const float*)d_in[7];
    const float* bhh1 = (const float*)d_in[8];
    float* out = (float*)d_out;

    cudaFuncSetAttribute(lstm_seq_kernel,
                         cudaFuncAttributeMaxDynamicSharedMemorySize, DYN_SMEM);

    // ---- layer 0 ----
    permute_kernel<<<2048, 256>>>(Wih0, Whh0, bih0, bhh0, I_);
    gemm_xp_kernel<<<dim3(16, 512), 256>>>(x, I_, 0);
    zero_hc_kernel<<<(BH_ + 255) / 256, 256>>>();
    lstm_seq_kernel<<<128, 256, DYN_SMEM>>>(0, out);

    // ---- layer 1 ----
    permute_kernel<<<2048, 256>>>(Wih1, Whh1, bih1, bhh1, H_);
    gemm_xp_kernel<<<dim3(16, 512), 256>>>(nullptr, H_, 1);
    zero_hc_kernel<<<(BH_ + 255) / 256, 256>>>();
    lstm_seq_kernel<<<128, 256, DYN_SMEM>>>(1, out);
}